// round 1
// baseline (speedup 1.0000x reference)
#include <cuda_runtime.h>

#define B_DIM 16
#define C_DIM 256
#define N_DIM 16384
#define K_DIM 8
#define NB 64
#define NTILES (N_DIM / NB)     // 256
#define NSTAGES 10
#define KAPPA 20.0f

// SMEM layout (floats):
//  s_x : [256][65]            = 16640   (pad 65 -> conflict-free column reads)
//  s_mu: [4][64*8 + 8] = 4*520 = 2080   (per-cg pad -> distinct banks per cg)
//  s_z : [64][8]              = 512
#define S_X_F   (256 * 65)
#define S_MU_F  (4 * 520)
#define S_Z_F   (64 * 8)
#define SMEM_BYTES ((S_X_F + S_MU_F + S_Z_F) * 4)

__device__ float g_mu[B_DIM * C_DIM * K_DIM];  // [b][c][k]
__device__ float g_M [B_DIM * C_DIM * K_DIM];  // accumulator [b][c][k]
__device__ float g_S [B_DIM * K_DIM];          // z column sums [b][k]

__device__ __forceinline__ float2 ffma2(float2 a, float2 b, float2 c) {
    float2 d;
    asm("fma.rn.f32x2 %0, %1, %2, %3;"
        : "=l"(reinterpret_cast<unsigned long long&>(d))
        : "l"(reinterpret_cast<unsigned long long&>(a)),
          "l"(reinterpret_cast<unsigned long long&>(b)),
          "l"(reinterpret_cast<unsigned long long&>(c)));
    return d;
}

__global__ void init_kernel(const float* __restrict__ mu_in) {
    int idx = blockIdx.x * blockDim.x + threadIdx.x;     // 32768 threads
    if (idx < B_DIM * C_DIM * K_DIM) {
        g_mu[idx] = mu_in[idx & (C_DIM * K_DIM - 1)];    // broadcast over b
        g_M[idx]  = 0.0f;
    }
    if (idx < B_DIM * K_DIM) g_S[idx] = 0.0f;
}

__global__ __launch_bounds__(256, 2)
void em_stage(const float* __restrict__ x, int last, float* __restrict__ z_out) {
    extern __shared__ float sm[];
    float* s_x  = sm;
    float* s_mu = sm + S_X_F;
    float* s_z  = sm + S_X_F + S_MU_F;

    const int tid = threadIdx.x;
    const int b   = blockIdx.y;
    const int n0  = blockIdx.x * NB;

    const float* xb = x + (size_t)b * C_DIM * N_DIM;

    // ---- load x tile [256 c][64 n] with float4 gmem reads ----
    #pragma unroll
    for (int it = 0; it < (C_DIM * NB / 4) / 256; ++it) {   // 16 iters
        int i = it * 256 + tid;        // quad index
        int c = i >> 4;                // 16 float4 per row
        int q = i & 15;
        float4 v = *reinterpret_cast<const float4*>(xb + (size_t)c * N_DIM + n0 + q * 4);
        float* d = s_x + c * 65 + q * 4;
        d[0] = v.x; d[1] = v.y; d[2] = v.z; d[3] = v.w;
    }
    // ---- load mu into padded per-cg layout ----
    #pragma unroll
    for (int it = 0; it < (C_DIM * K_DIM) / 256; ++it) {    // 8 iters
        int i = it * 256 + tid;
        int c = i >> 3, k = i & 7;
        s_mu[(c >> 6) * 520 + (c & 63) * 8 + k] = g_mu[b * (C_DIM * K_DIM) + i];
    }
    __syncthreads();

    // ---- phase 1: logits, softmax, z, S ----
    const int n  = tid >> 2;     // 0..63
    const int cg = tid & 3;      // 0..3  (low lane bits -> shfl-reducible)
    float2 a0 = {0.f,0.f}, a1 = {0.f,0.f}, a2 = {0.f,0.f}, a3 = {0.f,0.f};
    {
        const float*  xp  = s_x + (cg * 64) * 65 + n;
        const float4* mp4 = reinterpret_cast<const float4*>(s_mu + cg * 520);
        #pragma unroll 16
        for (int i = 0; i < 64; ++i) {
            float  xv = xp[i * 65];
            float2 xs = make_float2(xv, xv);
            float4 ma = mp4[i * 2 + 0];
            float4 mb = mp4[i * 2 + 1];
            a0 = ffma2(xs, make_float2(ma.x, ma.y), a0);
            a1 = ffma2(xs, make_float2(ma.z, ma.w), a1);
            a2 = ffma2(xs, make_float2(mb.x, mb.y), a2);
            a3 = ffma2(xs, make_float2(mb.z, mb.w), a3);
        }
    }
    // reduce partial dots over the 4 c-groups (xor offsets 1,2)
    #pragma unroll
    for (int off = 1; off <= 2; off <<= 1) {
        a0.x += __shfl_xor_sync(0xffffffffu, a0.x, off);
        a0.y += __shfl_xor_sync(0xffffffffu, a0.y, off);
        a1.x += __shfl_xor_sync(0xffffffffu, a1.x, off);
        a1.y += __shfl_xor_sync(0xffffffffu, a1.y, off);
        a2.x += __shfl_xor_sync(0xffffffffu, a2.x, off);
        a2.y += __shfl_xor_sync(0xffffffffu, a2.y, off);
        a3.x += __shfl_xor_sync(0xffffffffu, a3.x, off);
        a3.y += __shfl_xor_sync(0xffffffffu, a3.y, off);
    }

    if (cg == 0) {
        float l0 = KAPPA * a0.x, l1 = KAPPA * a0.y, l2 = KAPPA * a1.x, l3 = KAPPA * a1.y;
        float l4 = KAPPA * a2.x, l5 = KAPPA * a2.y, l6 = KAPPA * a3.x, l7 = KAPPA * a3.y;
        float m = fmaxf(fmaxf(fmaxf(l0,l1), fmaxf(l2,l3)), fmaxf(fmaxf(l4,l5), fmaxf(l6,l7)));
        float e0 = __expf(l0 - m), e1 = __expf(l1 - m), e2 = __expf(l2 - m), e3 = __expf(l3 - m);
        float e4 = __expf(l4 - m), e5 = __expf(l5 - m), e6 = __expf(l6 - m), e7 = __expf(l7 - m);
        float s = ((e0 + e1) + (e2 + e3)) + ((e4 + e5) + (e6 + e7));
        float inv = 1.0f / s;
        float z0 = e0*inv, z1 = e1*inv, z2 = e2*inv, z3 = e3*inv;
        float z4 = e4*inv, z5 = e5*inv, z6 = e6*inv, z7 = e7*inv;

        float* zp = s_z + n * 8;
        zp[0] = z0; zp[1] = z1; zp[2] = z2; zp[3] = z3;
        zp[4] = z4; zp[5] = z5; zp[6] = z6; zp[7] = z7;

        if (last) {
            float4* o = reinterpret_cast<float4*>(z_out + ((size_t)b * N_DIM + n0 + n) * 8);
            o[0] = make_float4(z0, z1, z2, z3);
            o[1] = make_float4(z4, z5, z6, z7);
        }

        // S partial reduce among active lanes (0,4,...,28 of each warp)
        const unsigned msk = 0x11111111u;
        float v0 = z0, v1 = z1, v2 = z2, v3 = z3, v4 = z4, v5 = z5, v6 = z6, v7 = z7;
        #pragma unroll
        for (int off = 4; off <= 16; off <<= 1) {
            v0 += __shfl_xor_sync(msk, v0, off);
            v1 += __shfl_xor_sync(msk, v1, off);
            v2 += __shfl_xor_sync(msk, v2, off);
            v3 += __shfl_xor_sync(msk, v3, off);
            v4 += __shfl_xor_sync(msk, v4, off);
            v5 += __shfl_xor_sync(msk, v5, off);
            v6 += __shfl_xor_sync(msk, v6, off);
            v7 += __shfl_xor_sync(msk, v7, off);
        }
        if ((tid & 31) == 0) {
            float* Sp = g_S + b * K_DIM;
            atomicAdd(Sp + 0, v0); atomicAdd(Sp + 1, v1);
            atomicAdd(Sp + 2, v2); atomicAdd(Sp + 3, v3);
            atomicAdd(Sp + 4, v4); atomicAdd(Sp + 5, v5);
            atomicAdd(Sp + 6, v6); atomicAdd(Sp + 7, v7);
        }
    }
    __syncthreads();

    // ---- phase 2: M[c][k] += sum_t x[c][t] * z[t][k] (tile-local rank-K update) ----
    {
        const int c = tid;
        float2 m0 = {0.f,0.f}, m1 = {0.f,0.f}, m2 = {0.f,0.f}, m3 = {0.f,0.f};
        const float*  xr  = s_x + c * 65;
        const float4* zz4 = reinterpret_cast<const float4*>(s_z);
        #pragma unroll 16
        for (int t = 0; t < 64; ++t) {
            float  xv = xr[t];
            float2 xs = make_float2(xv, xv);
            float4 za = zz4[t * 2 + 0];
            float4 zb = zz4[t * 2 + 1];
            m0 = ffma2(xs, make_float2(za.x, za.y), m0);
            m1 = ffma2(xs, make_float2(za.z, za.w), m1);
            m2 = ffma2(xs, make_float2(zb.x, zb.y), m2);
            m3 = ffma2(xs, make_float2(zb.z, zb.w), m3);
        }
        float* Mp = g_M + ((size_t)b * C_DIM + c) * K_DIM;
        atomicAdd(Mp + 0, m0.x); atomicAdd(Mp + 1, m0.y);
        atomicAdd(Mp + 2, m1.x); atomicAdd(Mp + 3, m1.y);
        atomicAdd(Mp + 4, m2.x); atomicAdd(Mp + 5, m2.y);
        atomicAdd(Mp + 6, m3.x); atomicAdd(Mp + 7, m3.y);
    }
}

// mu_new[c][k] = (M[c][k] / (1e-6 + S[k])) then L2-normalized over c; zero accumulators.
__global__ void finalize_kernel(int last, float* __restrict__ mu_out) {
    const int k = blockIdx.x;   // 0..7
    const int b = blockIdx.y;   // 0..15
    const int c = threadIdx.x;  // 0..255
    __shared__ float red[256];

    float S = g_S[b * K_DIM + k];
    float val = g_M[((size_t)b * C_DIM + c) * K_DIM + k] / (1e-6f + S);

    red[c] = val * val;
    __syncthreads();
    for (int s = 128; s > 0; s >>= 1) {
        if (c < s) red[c] += red[c + s];
        __syncthreads();
    }
    float norm = sqrtf(red[0]);
    float m = val / (1e-6f + norm);

    g_mu[((size_t)b * C_DIM + c) * K_DIM + k] = m;
    g_M [((size_t)b * C_DIM + c) * K_DIM + k] = 0.0f;
    if (c == 0) g_S[b * K_DIM + k] = 0.0f;
    if (last) mu_out[((size_t)b * K_DIM + k) * C_DIM + c] = m;  // [b][k][c]
}

// z_ = z / (1e-6 + S[b][k]) elementwise over [16,16384,8]
__global__ void zdiv_kernel(float* __restrict__ z) {
    int idx = blockIdx.x * blockDim.x + threadIdx.x;
    if (idx < B_DIM * N_DIM * K_DIM) {
        int k = idx & 7;
        int b = idx >> 17;  // 16384*8 = 2^17
        z[idx] = z[idx] / (1e-6f + g_S[b * K_DIM + k]);
    }
}

extern "C" void kernel_launch(void* const* d_in, const int* in_sizes, int n_in,
                              void* d_out, int out_size) {
    const float* x     = (const float*)d_in[0];   // [16,256,128,128]
    const float* mu_in = (const float*)d_in[1];   // [1,256,8]
    float* out    = (float*)d_out;
    float* mu_out = out;                              // [16,8,256]
    float* z_out  = out + B_DIM * K_DIM * C_DIM;      // [16,16384,8]

    cudaFuncSetAttribute(em_stage, cudaFuncAttributeMaxDynamicSharedMemorySize, SMEM_BYTES);

    init_kernel<<<128, 256>>>(mu_in);
    for (int s = 0; s < NSTAGES; ++s) {
        int last = (s == NSTAGES - 1);
        em_stage<<<dim3(NTILES, B_DIM), 256, SMEM_BYTES>>>(x, last, z_out);
        if (last) zdiv_kernel<<<(B_DIM * N_DIM * K_DIM) / 256, 256>>>(z_out);
        finalize_kernel<<<dim3(K_DIM, B_DIM), 256>>>(last, mu_out);
    }
}

// round 2
// speedup vs baseline: 1.6347x; 1.6347x over previous
#include <cuda_runtime.h>

#define B_DIM 16
#define C_DIM 256
#define N_DIM 16384
#define K_DIM 8
#define NB 32
#define NTILES (N_DIM / NB)          // 512 tiles per b
#define GR 18                        // blocks per b (grid stride)
#define NSTAGES 10
#define KAPPA 20.0f

// ---- smem layout (floats) ----
// x tile: addr(c,n) = c*33 + 2*(c>>4) + n   (conflict-free for both phases)
#define SX_SIZE 8480                 // 255*33 + 30 + 32, padded
#define MU_OFF  (2 * SX_SIZE)        // 16960
#define MU_SIZE 2112                 // addr(c,k) = c*8 + 4*(c>>4)
#define Z_OFF   (MU_OFF + MU_SIZE)   // 19072 ; z[n][k], 32*8
#define M_OFF   (Z_OFF + 256)        // 19328 ; s_M[h][c][k] = 2*256*8
#define S_OFF   (M_OFF + 4096)       // 23424 ; s_S[8]
#define SM_FLOATS (S_OFF + 8)
#define SMEM_BYTES (SM_FLOATS * 4)

__device__ float g_mu[B_DIM * C_DIM * K_DIM];  // [b][c][k]
__device__ float g_M [B_DIM * C_DIM * K_DIM];  // accumulator [b][c][k]
__device__ float g_S [B_DIM * K_DIM];          // z column sums [b][k]

__device__ __forceinline__ float2 ffma2(float2 a, float2 b, float2 c) {
    float2 d;
    asm("fma.rn.f32x2 %0, %1, %2, %3;"
        : "=l"(reinterpret_cast<unsigned long long&>(d))
        : "l"(reinterpret_cast<unsigned long long&>(a)),
          "l"(reinterpret_cast<unsigned long long&>(b)),
          "l"(reinterpret_cast<unsigned long long&>(c)));
    return d;
}

__device__ __forceinline__ int SX(int c, int n) { return c * 33 + ((c >> 4) << 1) + n; }
__device__ __forceinline__ int MU(int c)        { return c * 8  + ((c >> 4) << 2); }

__global__ void init_kernel(const float* __restrict__ mu_in) {
    int idx = blockIdx.x * blockDim.x + threadIdx.x;
    if (idx < B_DIM * C_DIM * K_DIM) {
        g_mu[idx] = mu_in[idx & (C_DIM * K_DIM - 1)];
        g_M[idx]  = 0.0f;
    }
    if (idx < B_DIM * K_DIM) g_S[idx] = 0.0f;
}

__global__ __launch_bounds__(512, 2)
void em_stage(const float* __restrict__ x, int last, float* __restrict__ z_out) {
    extern __shared__ float sm[];
    float* s_mu = sm + MU_OFF;
    float* s_z  = sm + Z_OFF;
    float* s_M  = sm + M_OFF;
    float* s_S  = sm + S_OFF;

    const int tid = threadIdx.x;
    const int b   = blockIdx.y;
    const float* xb = x + (size_t)b * C_DIM * N_DIM;

    // loader mapping: c = tid>>1, h = tid&1 ; 16 floats each
    const int lc = tid >> 1;
    const int lh = tid & 1;
    const size_t gbase = (size_t)lc * N_DIM + lh * 16;

    // phase-1 mapping: tid = n*16 + cg
    const int p1n  = tid >> 4;
    const int p1cg = tid & 15;

    // ---- prologue: mu, zero accum, first tile ----
    #pragma unroll
    for (int it = 0; it < 4; ++it) {
        int i = it * 512 + tid;      // 2048 mu elems
        s_mu[MU(i >> 3) + (i & 7)] = g_mu[b * (C_DIM * K_DIM) + i];
    }
    #pragma unroll
    for (int it = 0; it < 8; ++it) s_M[it * 512 + tid] = 0.0f;
    if (tid < 8) s_S[tid] = 0.0f;

    int t0 = blockIdx.x;             // first tile index
    float4 p0, p1, p2, p3;
    {
        const float* g = xb + gbase + (size_t)t0 * NB;
        p0 = *(const float4*)(g + 0);  p1 = *(const float4*)(g + 4);
        p2 = *(const float4*)(g + 8);  p3 = *(const float4*)(g + 12);
        float* d = sm + SX(lc, lh * 16);
        d[0]=p0.x; d[1]=p0.y; d[2]=p0.z; d[3]=p0.w;
        d[4]=p1.x; d[5]=p1.y; d[6]=p1.z; d[7]=p1.w;
        d[8]=p2.x; d[9]=p2.y; d[10]=p2.z; d[11]=p2.w;
        d[12]=p3.x; d[13]=p3.y; d[14]=p3.z; d[15]=p3.w;
    }
    if (t0 + GR < NTILES) {
        const float* g = xb + gbase + (size_t)(t0 + GR) * NB;
        p0 = *(const float4*)(g + 0);  p1 = *(const float4*)(g + 4);
        p2 = *(const float4*)(g + 8);  p3 = *(const float4*)(g + 12);
    }
    __syncthreads();

    int cur = 0;
    for (int t = t0; t < NTILES; t += GR) {
        float* s_x = sm + cur * SX_SIZE;

        // ================= phase 1 =================
        float2 a0 = {0.f,0.f}, a1 = {0.f,0.f}, a2 = {0.f,0.f}, a3 = {0.f,0.f};
        {
            const float* xp = s_x + p1cg * 530 + p1n;     // 528 + 2 skew
            const float* mp = s_mu + p1cg * 132;
            #pragma unroll
            for (int i = 0; i < 16; ++i) {
                float  xv = xp[i * 33];
                float2 xs = make_float2(xv, xv);
                float4 ma = *(const float4*)(mp + i * 8);
                float4 mb = *(const float4*)(mp + i * 8 + 4);
                a0 = ffma2(xs, make_float2(ma.x, ma.y), a0);
                a1 = ffma2(xs, make_float2(ma.z, ma.w), a1);
                a2 = ffma2(xs, make_float2(mb.x, mb.y), a2);
                a3 = ffma2(xs, make_float2(mb.z, mb.w), a3);
            }
        }
        #pragma unroll
        for (int off = 1; off <= 8; off <<= 1) {
            a0.x += __shfl_xor_sync(~0u, a0.x, off);
            a0.y += __shfl_xor_sync(~0u, a0.y, off);
            a1.x += __shfl_xor_sync(~0u, a1.x, off);
            a1.y += __shfl_xor_sync(~0u, a1.y, off);
            a2.x += __shfl_xor_sync(~0u, a2.x, off);
            a2.y += __shfl_xor_sync(~0u, a2.y, off);
            a3.x += __shfl_xor_sync(~0u, a3.x, off);
            a3.y += __shfl_xor_sync(~0u, a3.y, off);
        }
        if (p1cg == 0) {
            float l0 = KAPPA*a0.x, l1 = KAPPA*a0.y, l2 = KAPPA*a1.x, l3 = KAPPA*a1.y;
            float l4 = KAPPA*a2.x, l5 = KAPPA*a2.y, l6 = KAPPA*a3.x, l7 = KAPPA*a3.y;
            float m = fmaxf(fmaxf(fmaxf(l0,l1), fmaxf(l2,l3)),
                            fmaxf(fmaxf(l4,l5), fmaxf(l6,l7)));
            float e0 = __expf(l0-m), e1 = __expf(l1-m), e2 = __expf(l2-m), e3 = __expf(l3-m);
            float e4 = __expf(l4-m), e5 = __expf(l5-m), e6 = __expf(l6-m), e7 = __expf(l7-m);
            float inv = 1.0f / (((e0+e1)+(e2+e3)) + ((e4+e5)+(e6+e7)));
            float4* zp = (float4*)(s_z + p1n * 8);
            zp[0] = make_float4(e0*inv, e1*inv, e2*inv, e3*inv);
            zp[1] = make_float4(e4*inv, e5*inv, e6*inv, e7*inv);
        }
        __syncthreads();

        // ================= phase 2 (+ prefetch STS/LDG) =================
        if (last && tid < 64) {
            int n = tid >> 1, q = tid & 1;
            float4 zv = *(const float4*)(s_z + n * 8 + q * 4);
            *(float4*)(z_out + ((size_t)b * N_DIM + (size_t)t * NB + n) * 8 + q * 4) = zv;
        }
        if (tid < 8) {   // S accumulation for this tile
            float s = 0.f;
            #pragma unroll
            for (int n = 0; n < NB; ++n) s += s_z[n * 8 + tid];
            s_S[tid] += s;
        }
        {
            float2 m0 = {0.f,0.f}, m1 = {0.f,0.f}, m2 = {0.f,0.f}, m3 = {0.f,0.f};
            const float*  xr = s_x + SX(lc, lh * 16);
            const float4* zz = (const float4*)(s_z + lh * 128);
            #pragma unroll
            for (int j = 0; j < 16; ++j) {
                float  xv = xr[j];
                float2 xs = make_float2(xv, xv);
                float4 za = zz[2*j], zb = zz[2*j+1];
                m0 = ffma2(xs, make_float2(za.x, za.y), m0);
                m1 = ffma2(xs, make_float2(za.z, za.w), m1);
                m2 = ffma2(xs, make_float2(zb.x, zb.y), m2);
                m3 = ffma2(xs, make_float2(zb.z, zb.w), m3);
            }
            float4* Mp = (float4*)(s_M + ((lh << 11) | (lc << 3)));
            float4 old0 = Mp[0], old1 = Mp[1];
            Mp[0] = make_float4(old0.x+m0.x, old0.y+m0.y, old0.z+m1.x, old0.w+m1.y);
            Mp[1] = make_float4(old1.x+m2.x, old1.y+m2.y, old1.z+m3.x, old1.w+m3.y);
        }
        // stage tile t+GR into the other buffer; prefetch t+2*GR
        if (t + GR < NTILES) {
            float* d = sm + (cur ^ 1) * SX_SIZE + SX(lc, lh * 16);
            d[0]=p0.x; d[1]=p0.y; d[2]=p0.z; d[3]=p0.w;
            d[4]=p1.x; d[5]=p1.y; d[6]=p1.z; d[7]=p1.w;
            d[8]=p2.x; d[9]=p2.y; d[10]=p2.z; d[11]=p2.w;
            d[12]=p3.x; d[13]=p3.y; d[14]=p3.z; d[15]=p3.w;
            if (t + 2 * GR < NTILES) {
                const float* g = xb + gbase + (size_t)(t + 2 * GR) * NB;
                p0 = *(const float4*)(g + 0);  p1 = *(const float4*)(g + 4);
                p2 = *(const float4*)(g + 8);  p3 = *(const float4*)(g + 12);
            }
        }
        __syncthreads();
        cur ^= 1;
    }

    // ---- epilogue: flush block-local accumulators ----
    if (tid < 8) atomicAdd(g_S + b * K_DIM + tid, s_S[tid]);
    #pragma unroll
    for (int it = 0; it < 4; ++it) {
        int i = it * 512 + tid;          // (c,k) pair index, 2048 total
        float v = s_M[i] + s_M[2048 + i];
        atomicAdd(g_M + b * (C_DIM * K_DIM) + i, v);
    }
}

__global__ void finalize_kernel(int last, float* __restrict__ mu_out) {
    const int k = blockIdx.x;
    const int b = blockIdx.y;
    const int c = threadIdx.x;
    __shared__ float red[256];

    float S = g_S[b * K_DIM + k];
    float val = g_M[((size_t)b * C_DIM + c) * K_DIM + k] / (1e-6f + S);

    red[c] = val * val;
    __syncthreads();
    for (int s = 128; s > 0; s >>= 1) {
        if (c < s) red[c] += red[c + s];
        __syncthreads();
    }
    float m = val / (1e-6f + sqrtf(red[0]));

    g_mu[((size_t)b * C_DIM + c) * K_DIM + k] = m;
    g_M [((size_t)b * C_DIM + c) * K_DIM + k] = 0.0f;
    if (c == 0) g_S[b * K_DIM + k] = 0.0f;
    if (last) mu_out[((size_t)b * K_DIM + k) * C_DIM + c] = m;
}

__global__ void zdiv_kernel(float* __restrict__ z) {
    int idx = blockIdx.x * blockDim.x + threadIdx.x;
    if (idx < B_DIM * N_DIM * K_DIM) {
        int k = idx & 7;
        int b = idx >> 17;
        z[idx] = z[idx] / (1e-6f + g_S[b * K_DIM + k]);
    }
}

extern "C" void kernel_launch(void* const* d_in, const int* in_sizes, int n_in,
                              void* d_out, int out_size) {
    const float* x     = (const float*)d_in[0];
    const float* mu_in = (const float*)d_in[1];
    float* out    = (float*)d_out;
    float* mu_out = out;
    float* z_out  = out + B_DIM * K_DIM * C_DIM;

    cudaFuncSetAttribute(em_stage, cudaFuncAttributeMaxDynamicSharedMemorySize, SMEM_BYTES);

    init_kernel<<<128, 256>>>(mu_in);
    for (int s = 0; s < NSTAGES; ++s) {
        int last = (s == NSTAGES - 1);
        em_stage<<<dim3(GR, B_DIM), 512, SMEM_BYTES>>>(x, last, z_out);
        if (last) zdiv_kernel<<<(B_DIM * N_DIM * K_DIM) / 256, 256>>>(z_out);
        finalize_kernel<<<dim3(K_DIM, B_DIM), 256>>>(last, mu_out);
    }
}